// round 17
// baseline (speedup 1.0000x reference)
#include <cuda_runtime.h>
#include <cuda_bf16.h>
#include <math.h>

// Problem constants (fixed by setup_inputs): B=32, N=M=1024, F=4
#define BB    32
#define NN    1024
#define MM    1024
#define BT    256             // block threads (8 warps -> 2 per SMSP)
#define RR    4               // rows per thread (256*4 = 1024)
#define UU    2               // batches per CTA (ILP fill)
#define NG    (MM / 2)        // 512 column groups (2 cols per group)
#define NWARP (BT / 32)       // 8

// Epoch-skew parameters: barrier every KS steps; warp boundary gap = KS.
#define KS      8
#define WSKEW   (32 + KS - 1)                 // 39: sigma = lane + 39*warp
#define SIGMAX  (31 + WSKEW * (NWARP - 1))    // 304
#define STEPS   (NG + SIGMAX)                 // 816 (multiple of 8; last cell at s=815)
#define EPOCHS  (STEPS / KS)                  // 102

__device__ float g_loss[BB];
__device__ int   g_done;     // zero-init; self-resetting each launch

__device__ __forceinline__ float fsqrt_approx(float x) {
    float r;
    asm("sqrt.approx.f32 %0, %1;" : "=f"(r) : "f"(x));
    return r;
}

__global__ __launch_bounds__(BT, 1)
void dtw_fused(const float* __restrict__ preds, const float* __restrict__ targs,
               const float* __restrict__ subcoef, float* __restrict__ out)
{
    const int bx   = blockIdx.x;              // batch pair: 2bx, 2bx+1
    const int tid  = threadIdx.x;
    const int lane = tid & 31;
    const int warp = tid >> 5;
    const int sig  = lane + WSKEW * warp;     // thread skew
    const int wlo  = WSKEW * warp;            // warp-uniform active window
    const int whi  = wlo + 31 + NG;           // [wlo, whi)
    const bool l0  = (lane == 0);

    __shared__ float2 txy[UU][MM];            // 16 KB target basis (2 batches)
    // Boundary-padded handoff slots (slot 0 constant, producer w writes w+1)
    __shared__ float4 sbD[UU][2][KS][NWARP];
    __shared__ float4 sbA[UU][2][KS][NWARP];

    const float INF = __int_as_float(0x7f800000);
    const float c0s = subcoef[0];
    const float c1s = subcoef[1];

    // ---- init ----
    #pragma unroll
    for (int u = 0; u < UU; ++u) {
        const float* tb = targs + (size_t)(UU * bx + u) * MM * 4;
        for (int idx = tid; idx < MM; idx += BT)
            txy[u][idx] = *(const float2*)(tb + (size_t)idx * 4);
        for (int idx = tid; idx < 2 * KS * NWARP; idx += BT) {
            ((float4*)sbD[u])[idx] = make_float4(INF, INF, INF, INF);
            ((float4*)sbA[u])[idx] = make_float4(0.0f, 0.0f, 0.0f, 0.0f);
        }
    }

    float px[UU][RR], py[UU][RR], left[UU][RR], Aleft[UU][RR];
    #pragma unroll
    for (int u = 0; u < UU; ++u) {
        const float* pbu = preds + (size_t)(UU * bx + u) * NN * 4;
        #pragma unroll
        for (int q = 0; q < RR; ++q) {
            const float2 pv = *(const float2*)(pbu + (size_t)(tid * RR + q) * 4);
            px[u][q] = pv.x; py[u][q] = pv.y;
            left[u][q]  = INF;
            Aleft[u][q] = 0.0f;
        }
    }
    __syncthreads();

    // =====================================================================
    // Two independent forward DPs (batches 2bx, 2bx+1) in one warp set:
    // thread owns rows 4t..4t+3 of both; at step s it processes column group
    // g = s - sigma (columns 2g, 2g+1) for each batch, carrying
    //   D[i,j] = cost(i,j) + min(D[i-1,j-1], D[i-1,j], D[i,j-1])
    //   A[i,j] = A[argmin parent] + |dx|*c0 + |dy|*c1
    // The two recursions are data-independent -> their serial fmin/fadd
    // chains interleave and fill each other's latency stalls.
    // Handoff: 8 shfls + branchless lane0 merge from boundary-padded slots;
    // diag operands cached from previous step's nb1/na1. Barrier per KS steps.
    // =====================================================================
    float bot0[UU], bot1[UU], Ab0[UU], Ab1[UU], cnb1[UU], cna1[UU];
    #pragma unroll
    for (int u = 0; u < UU; ++u) {
        bot0[u] = INF; bot1[u] = INF; Ab0[u] = 0.0f; Ab1[u] = 0.0f;
        cnb1[u] = INF; cna1[u] = 0.0f;
    }

    for (int e = 0; e < EPOCHS; ++e) {
        const int par = e & 1;
        #pragma unroll
        for (int ks = 0; ks < KS; ++ks) {
            const int s = e * KS + ks;

            // ---- handoff (both batches, branchless) ----
            float nb0[UU], nb1[UU], na0[UU], na1[UU];
            #pragma unroll
            for (int u = 0; u < UU; ++u) {
                const float4 vD = sbD[u][par ^ 1][ks][warp];  // broadcast; slot0=boundary
                const float4 vA = sbA[u][par ^ 1][ks][warp];
                float b0 = __shfl_up_sync(0xffffffffu, bot0[u], 1);
                float b1 = __shfl_up_sync(0xffffffffu, bot1[u], 1);
                float a0 = __shfl_up_sync(0xffffffffu, Ab0[u], 1);
                float a1 = __shfl_up_sync(0xffffffffu, Ab1[u], 1);
                nb0[u] = l0 ? vD.x : b0;
                nb1[u] = l0 ? vD.y : b1;
                na0[u] = l0 ? vA.x : a0;
                na1[u] = l0 ? vA.y : a1;
            }

            // ---- DP bodies (warp-uniformly skipped outside active window) ----
            if (s >= wlo && s < whi) {
                const int g = s - sig;
                if ((unsigned)g < (unsigned)NG) {
                    const int c0 = g * 2;
                    #pragma unroll
                    for (int u = 0; u < UU; ++u) {
                        const float2 t0 = txy[u][c0];
                        const float2 t1 = txy[u][c0 + 1];

                        // ---- column c0 (diag from cache) ----
                        float up = nb0[u], dg = cnb1[u], Aup = na0[u], Adg = cna1[u];
                        float cur0[RR], Acur0[RR];
                        #pragma unroll
                        for (int q = 0; q < RR; ++q) {
                            const float lf  = left[u][q];
                            const float Alf = Aleft[u][q];
                            const float pm  = fminf(dg, lf);
                            float best = fminf(up, pm);
                            const bool p0 = (best == dg);
                            const bool p1 = (best == up);
                            const float Asel = p0 ? Adg : (p1 ? Aup : Alf);
                            if (q == 0) best = (best == INF) ? 0.0f : best;  // (0,0) seed
                            const float dx = px[u][q] - t0.x;
                            const float dy = py[u][q] - t0.y;
                            const float cst = fsqrt_approx(fmaf(dx, dx, dy * dy));
                            const float lcv = fmaf(fabsf(dy), c1s, fabsf(dx) * c0s);
                            const float cur  = best + cst;
                            const float Acur = Asel + lcv;
                            dg = lf;  Adg = Alf;
                            up = cur; Aup = Acur;
                            cur0[q] = cur; Acur0[q] = Acur;
                        }

                        // ---- column c0+1 ----
                        up = nb1[u]; dg = nb0[u]; Aup = na1[u]; Adg = na0[u];
                        #pragma unroll
                        for (int q = 0; q < RR; ++q) {
                            const float lf  = cur0[q];
                            const float Alf = Acur0[q];
                            const float pm  = fminf(dg, lf);
                            const float best = fminf(up, pm);
                            const bool p0 = (best == dg);
                            const bool p1 = (best == up);
                            const float Asel = p0 ? Adg : (p1 ? Aup : Alf);
                            const float dx = px[u][q] - t1.x;
                            const float dy = py[u][q] - t1.y;
                            const float cst = fsqrt_approx(fmaf(dx, dx, dy * dy));
                            const float lcv = fmaf(fabsf(dy), c1s, fabsf(dx) * c0s);
                            const float cur  = best + cst;
                            const float Acur = Asel + lcv;
                            dg = lf;  Adg = Alf;
                            up = cur; Aup = Acur;
                            left[u][q] = cur; Aleft[u][q] = Acur;
                        }

                        bot0[u] = cur0[RR - 1];    Ab0[u] = Acur0[RR - 1];
                        bot1[u] = left[u][RR - 1]; Ab1[u] = Aleft[u][RR - 1];
                    }
                }
            }

            // producer: lane 31 of warps 0..6 posts into slot warp+1
            if (lane == 31 && warp < NWARP - 1) {
                #pragma unroll
                for (int u = 0; u < UU; ++u) {
                    sbD[u][par][ks][warp + 1] = make_float4(bot0[u], bot1[u], 0.0f, 0.0f);
                    sbA[u][par][ks][warp + 1] = make_float4(Ab0[u],  Ab1[u],  0.0f, 0.0f);
                }
            }

            // update diag caches AFTER use
            #pragma unroll
            for (int u = 0; u < UU; ++u) { cnb1[u] = nb1[u]; cna1[u] = na1[u]; }
        }
        __syncthreads();
    }

    // ---- result: thread BT-1 holds A at (NN-1, MM-1) for both batches ----
    if (tid == BT - 1) {
        #pragma unroll
        for (int u = 0; u < UU; ++u)
            g_loss[UU * bx + u] = Ab1[u];
        __threadfence();
        const int old = atomicAdd(&g_done, 1);
        if (old == BB / UU - 1) {
            __threadfence();
            float t2 = 0.0f;
            #pragma unroll
            for (int x = 0; x < BB; ++x) t2 += g_loss[x];
            out[0] = t2;
            g_done = 0;   // self-reset for next graph replay
        }
    }
}

extern "C" void kernel_launch(void* const* d_in, const int* in_sizes, int n_in,
                              void* d_out, int out_size)
{
    const float* preds   = (const float*)d_in[0];
    const float* targs   = (const float*)d_in[1];
    const float* subcoef = (const float*)d_in[2];
    float* out = (float*)d_out;

    dtw_fused<<<BB / UU, BT>>>(preds, targs, subcoef, out);
}